// round 1
// baseline (speedup 1.0000x reference)
#include <cuda_runtime.h>
#include <cuda_bf16.h>

// GroupLasso collapses algebraically:
//   result = (0.02 + 0.04 + 0.06) * (sum(W^2) + sum(b^2))
// because the coarse segment_sum partitions all rows (sum of segment sums ==
// total sum). So this is a single HBM-bound sum-of-squares reduction over
// ~51.3M fp32 values (204.8 MB).

#define TOTAL_GAMMA 0.12f

__global__ void gl_zero_kernel(float* __restrict__ out) {
    if (blockIdx.x == 0 && threadIdx.x == 0) out[0] = 0.0f;
}

__global__ __launch_bounds__(256, 8)
void gl_reduce_kernel(const float4* __restrict__ w4, long long nw4,
                      const float4* __restrict__ b4, long long nb4,
                      float* __restrict__ out) {
    const long long tid    = (long long)blockIdx.x * blockDim.x + threadIdx.x;
    const long long stride = (long long)gridDim.x * blockDim.x;

    float acc = 0.0f;

    // Main body over weights: unrolled x4 grid-stride for deep MLP.
    long long i = tid;
    const long long nw4_4 = nw4 - 3 * stride;
    for (; i < nw4_4; i += 4 * stride) {
        float4 v0 = w4[i];
        float4 v1 = w4[i + stride];
        float4 v2 = w4[i + 2 * stride];
        float4 v3 = w4[i + 3 * stride];
        acc += v0.x * v0.x + v0.y * v0.y + v0.z * v0.z + v0.w * v0.w;
        acc += v1.x * v1.x + v1.y * v1.y + v1.z * v1.z + v1.w * v1.w;
        acc += v2.x * v2.x + v2.y * v2.y + v2.z * v2.z + v2.w * v2.w;
        acc += v3.x * v3.x + v3.y * v3.y + v3.z * v3.z + v3.w * v3.w;
    }
    for (; i < nw4; i += stride) {
        float4 v = w4[i];
        acc += v.x * v.x + v.y * v.y + v.z * v.z + v.w * v.w;
    }

    // Bias (small tail: 25K float4).
    for (long long j = tid; j < nb4; j += stride) {
        float4 v = b4[j];
        acc += v.x * v.x + v.y * v.y + v.z * v.z + v.w * v.w;
    }

    // Warp reduction.
    #pragma unroll
    for (int o = 16; o > 0; o >>= 1)
        acc += __shfl_xor_sync(0xFFFFFFFFu, acc, o);

    __shared__ float smem[8];  // 256 threads -> 8 warps
    const int lane = threadIdx.x & 31;
    const int wid  = threadIdx.x >> 5;
    if (lane == 0) smem[wid] = acc;
    __syncthreads();

    if (wid == 0) {
        float v = (lane < 8) ? smem[lane] : 0.0f;
        #pragma unroll
        for (int o = 4; o > 0; o >>= 1)
            v += __shfl_xor_sync(0xFFFFFFFFu, v, o);
        if (lane == 0)
            atomicAdd(out, v * TOTAL_GAMMA);
    }
}

extern "C" void kernel_launch(void* const* d_in, const int* in_sizes, int n_in,
                              void* d_out, int out_size) {
    const float* fc_weights = (const float*)d_in[0];   // [100000, 512] fp32
    const float* fc_bias    = (const float*)d_in[1];   // [100000] fp32
    // d_in[2] = coarse_map (int32) — provably unused (segments partition rows).

    const long long nw = (long long)in_sizes[0];  // 51,200,000 (divisible by 4)
    const long long nb = (long long)in_sizes[1];  // 100,000    (divisible by 4)

    float* out = (float*)d_out;

    gl_zero_kernel<<<1, 32>>>(out);

    const int threads = 256;
    const int blocks  = 148 * 8;  // 1184 blocks: full-chip, ~43 float4/thread
    gl_reduce_kernel<<<blocks, threads>>>(
        (const float4*)fc_weights, nw / 4,
        (const float4*)fc_bias,    nb / 4,
        out);
}

// round 2
// speedup vs baseline: 1.0009x; 1.0009x over previous
#include <cuda_runtime.h>
#include <cuda_bf16.h>

// GroupLasso collapses algebraically:
//   result = (0.02 + 0.04 + 0.06) * (sum(W^2) + sum(b^2))
// (the coarse segment_sum partitions all rows, so sum(segment_sums) == total).
// Pure HBM-bound sum-of-squares over 204.8 MB of fp32.
//
// Single kernel: block partials -> device scratch, last block finalizes
// (writes out[0] directly and resets the counter for graph replay).

#define TOTAL_GAMMA 0.12f
#define NBLOCKS (148 * 8)

__device__ float        g_partials[NBLOCKS];
__device__ unsigned int g_done_count = 0;

__global__ __launch_bounds__(256, 8)
void gl_reduce_kernel(const float4* __restrict__ w4, long long nw4,
                      const float4* __restrict__ b4, long long nb4,
                      float* __restrict__ out) {
    const long long tid    = (long long)blockIdx.x * blockDim.x + threadIdx.x;
    const long long stride = (long long)gridDim.x * blockDim.x;

    float acc = 0.0f;

    // Main body over weights: unrolled x4 grid-stride, streaming (evict-first)
    // loads -- data exceeds L2 and has zero reuse.
    long long i = tid;
    const long long nw4_4 = nw4 - 3 * stride;
    for (; i < nw4_4; i += 4 * stride) {
        float4 v0 = __ldcs(&w4[i]);
        float4 v1 = __ldcs(&w4[i + stride]);
        float4 v2 = __ldcs(&w4[i + 2 * stride]);
        float4 v3 = __ldcs(&w4[i + 3 * stride]);
        acc += v0.x * v0.x + v0.y * v0.y + v0.z * v0.z + v0.w * v0.w;
        acc += v1.x * v1.x + v1.y * v1.y + v1.z * v1.z + v1.w * v1.w;
        acc += v2.x * v2.x + v2.y * v2.y + v2.z * v2.z + v2.w * v2.w;
        acc += v3.x * v3.x + v3.y * v3.y + v3.z * v3.z + v3.w * v3.w;
    }
    for (; i < nw4; i += stride) {
        float4 v = __ldcs(&w4[i]);
        acc += v.x * v.x + v.y * v.y + v.z * v.z + v.w * v.w;
    }

    // Bias tail (25K float4).
    for (long long j = tid; j < nb4; j += stride) {
        float4 v = __ldcs(&b4[j]);
        acc += v.x * v.x + v.y * v.y + v.z * v.z + v.w * v.w;
    }

    // Warp reduction.
    #pragma unroll
    for (int o = 16; o > 0; o >>= 1)
        acc += __shfl_xor_sync(0xFFFFFFFFu, acc, o);

    __shared__ float smem[8];
    const int lane = threadIdx.x & 31;
    const int wid  = threadIdx.x >> 5;
    if (lane == 0) smem[wid] = acc;
    __syncthreads();

    __shared__ bool s_is_last;
    if (wid == 0) {
        float v = (lane < 8) ? smem[lane] : 0.0f;
        #pragma unroll
        for (int o = 4; o > 0; o >>= 1)
            v += __shfl_xor_sync(0xFFFFFFFFu, v, o);
        if (lane == 0) {
            g_partials[blockIdx.x] = v;
            __threadfence();
            unsigned int prev = atomicAdd(&g_done_count, 1u);
            s_is_last = (prev == (unsigned int)(gridDim.x - 1));
        }
    }
    __syncthreads();

    // Last block to finish: sum the partials, write out, reset the counter.
    if (s_is_last) {
        float v = 0.0f;
        for (int k = threadIdx.x; k < NBLOCKS; k += 256)
            v += g_partials[k];
        #pragma unroll
        for (int o = 16; o > 0; o >>= 1)
            v += __shfl_xor_sync(0xFFFFFFFFu, v, o);
        if (lane == 0) smem[wid] = v;
        __syncthreads();
        if (wid == 0) {
            float t = (lane < 8) ? smem[lane] : 0.0f;
            #pragma unroll
            for (int o = 4; o > 0; o >>= 1)
                t += __shfl_xor_sync(0xFFFFFFFFu, t, o);
            if (lane == 0) {
                out[0] = t * TOTAL_GAMMA;
                g_done_count = 0;  // reset for next graph replay
            }
        }
    }
}

extern "C" void kernel_launch(void* const* d_in, const int* in_sizes, int n_in,
                              void* d_out, int out_size) {
    const float* fc_weights = (const float*)d_in[0];   // [100000, 512] fp32
    const float* fc_bias    = (const float*)d_in[1];   // [100000] fp32
    // d_in[2] = coarse_map (int32) -- provably unused.

    const long long nw = (long long)in_sizes[0];  // 51,200,000 (div by 4)
    const long long nb = (long long)in_sizes[1];  // 100,000    (div by 4)

    gl_reduce_kernel<<<NBLOCKS, 256>>>(
        (const float4*)fc_weights, nw / 4,
        (const float4*)fc_bias,    nb / 4,
        (float*)d_out);
}